// round 9
// baseline (speedup 1.0000x reference)
#include <cuda_runtime.h>
#include <cuda_fp16.h>
#include <cstdint>

// Problem constants (fixed by setup_inputs)
#define BATCH 128
#define IC    2048
#define OC    32
#define OD    16
#define ROW   512          // OC*OD floats per (b,i) row
#define THREADS 256
#define WPB   8            // warps per block
#define BPB_I 8            // blocks per batch, init pass
#define BPB_T 32           // blocks per batch, iter passes (grid 4096)
#define IPW_I 32           // rows per warp, init
#define IPW_T 8            // rows per warp, iter

typedef unsigned long long u64;
#define LOG2E_F 1.4426950408889634f

// Scratch (device globals: allocation-free per harness rules)
__device__ __align__(16) __half g_u16[(size_t)BATCH * IC * ROW];    // 268 MB fp16 copy of u
__device__ __align__(16) float  g_part[(size_t)BATCH * BPB_T * ROW];// 8 MB block partials
__device__ __align__(16) float  g_vsum[(size_t)BATCH * ROW];        // 256 KB running v sum
__device__ __align__(16) float  g_bpre_t[(size_t)OC * IC];          // 256 KB bin^T * log2(e)
__device__ int g_cnt[BATCH];                                        // zero-init; self-resetting

__device__ __forceinline__ u64 pack_f2(float lo, float hi) {
    u64 r; asm("mov.b64 %0, {%1, %2};" : "=l"(r) : "f"(lo), "f"(hi)); return r;
}
__device__ __forceinline__ void unpack_f2(u64 v, float& lo, float& hi) {
    asm("mov.b64 {%0, %1}, %2;" : "=f"(lo), "=f"(hi) : "l"(v));
}
__device__ __forceinline__ void ffma2(u64& d, u64 a, u64 b) {
    asm("fma.rn.f32x2 %0, %1, %2, %0;" : "+l"(d) : "l"(a), "l"(b));
}
__device__ __forceinline__ float ex2a(float x) {
    float y; asm("ex2.approx.f32 %0, %1;" : "=f"(y) : "f"(x)); return y;
}
__device__ __forceinline__ float rcpa(float x) {
    float y; asm("rcp.approx.f32 %0, %1;" : "=f"(y) : "f"(x)); return y;
}

// Tiny one-shot: g_bpre_t[o][i] = bin[i][o] * log2(e)   (transposed prior table)
__global__ void rba_prescale(const float* __restrict__ bin)
{
    int idx = blockIdx.x * blockDim.x + threadIdx.x;   // idx = o*IC + i
    if (idx < IC * OC) {
        int o = idx >> 11;          // / IC
        int i = idx & (IC - 1);
        g_bpre_t[idx] = bin[(size_t)i * OC + o] * LOG2E_F;
    }
}

// Cross-block reduction + squash, after warp partials are in sred.
// NB = chunks per batch. mode 0: vsum = v; mode 1: vsum += v; mode 2: out = v.
template<int NB>
__device__ __forceinline__ void block_tail_reduce(float (*sred)[ROW], int b, int chunk,
                                                  int mode, float* __restrict__ out)
{
    __shared__ bool amLast;
    const int t = threadIdx.x;
    float r0 = 0.f, r1 = 0.f;
    #pragma unroll
    for (int w = 0; w < WPB; ++w) { r0 += sred[w][t]; r1 += sred[w][t + 256]; }
    float* bp = g_part + ((size_t)b * NB + chunk) * ROW;
    bp[t] = r0; bp[t + 256] = r1;

    __threadfence();
    __syncthreads();
    if (t == 0) {
        int old = atomicAdd(&g_cnt[b], 1);
        amLast = (old == NB - 1);
        if (amLast) g_cnt[b] = 0;      // replay-safe reset
    }
    __syncthreads();
    if (!amLast) return;
    __threadfence();                   // acquire: see all blocks' partials

    const float* pb = g_part + (size_t)b * NB * ROW;
    float s0 = 0.f, s1 = 0.f;
    #pragma unroll 8
    for (int c = 0; c < NB; ++c) {     // fixed order -> deterministic
        s0 += pb[(size_t)c * ROW + t];
        s1 += pb[(size_t)c * ROW + t + 256];
    }

    // squash: ||s||^2 over the 16 d-lanes of each o
    const unsigned FULL = 0xffffffffu;
    float q0 = s0 * s0, q1 = s1 * s1;
    #pragma unroll
    for (int m = 1; m < 16; m <<= 1) {
        q0 += __shfl_xor_sync(FULL, q0, m);
        q1 += __shfl_xor_sync(FULL, q1, m);
    }
    float v0 = s0 * sqrtf(q0) / (1.f + q0);
    float v1 = s1 * sqrtf(q1) / (1.f + q1);

    float* vs = g_vsum + (size_t)b * ROW;
    if (mode == 0)      { vs[t] = v0;            vs[t + 256] = v1; }
    else if (mode == 1) { vs[t] += v0;           vs[t + 256] += v1; }
    else                { out[(size_t)b * ROW + t] = v0;
                          out[(size_t)b * ROW + t + 256] = v1; }
}

// Init pass: c = softmax(b_in), s = sum_i c*u; emits fp16 copy of u.
// HBM-bound (804 MB) at ~7.5 TB/s already — structure unchanged.
__global__ __launch_bounds__(THREADS)
void rba_init(const float* __restrict__ u, const float* __restrict__ bin)
{
    __shared__ float sred[WPB][ROW];
    const int b     = blockIdx.x >> 3;
    const int chunk = blockIdx.x & 7;
    const int warp  = threadIdx.x >> 5;
    const int lane  = threadIdx.x & 31;
    const int g     = lane >> 2;
    const int wc    = chunk * WPB + warp;
    const unsigned FULL = 0xffffffffu;

    float4 acc[4];
    #pragma unroll
    for (int j = 0; j < 4; ++j) acc[j] = make_float4(0.f, 0.f, 0.f, 0.f);

    const size_t ubase = ((size_t)b * IC + (size_t)wc * IPW_I) * ROW;

    for (int ii = 0; ii < IPW_I; ++ii) {
        const int i = wc * IPW_I + ii;
        const float4* up = reinterpret_cast<const float4*>(u + ubase + (size_t)ii * ROW);
        __half* dst = g_u16 + ubase + (size_t)ii * ROW;

        float4 u4[4];
        #pragma unroll
        for (int j = 0; j < 4; ++j) u4[j] = up[j * 32 + lane];   // coalesced 2KB/row

        #pragma unroll
        for (int j = 0; j < 4; ++j) {
            union { uint2 raw; __half2 h[2]; } pk;
            pk.h[0] = __floats2half2_rn(u4[j].x, u4[j].y);
            pk.h[1] = __floats2half2_rn(u4[j].z, u4[j].w);
            *reinterpret_cast<uint2*>(dst + j * 128 + lane * 4) = pk.raw;
        }

        float bv = bin[(size_t)i * OC + lane];
        float logit[4];
        #pragma unroll
        for (int j = 0; j < 4; ++j) logit[j] = __shfl_sync(FULL, bv, j * 8 + g);

        float e[4], Z = 0.f;
        #pragma unroll
        for (int j = 0; j < 4; ++j) { e[j] = __expf(logit[j]); Z += e[j]; }
        Z += __shfl_xor_sync(FULL, Z, 4);
        Z += __shfl_xor_sync(FULL, Z, 8);
        Z += __shfl_xor_sync(FULL, Z, 16);
        float rZ = __frcp_rn(Z);
        #pragma unroll
        for (int j = 0; j < 4; ++j) {
            float c = e[j] * rZ;
            acc[j].x += c * u4[j].x; acc[j].y += c * u4[j].y;
            acc[j].z += c * u4[j].z; acc[j].w += c * u4[j].w;
        }
    }

    #pragma unroll
    for (int j = 0; j < 4; ++j)
        *reinterpret_cast<float4*>(&sred[warp][j * 128 + lane * 4]) = acc[j];
    __syncthreads();
    block_tail_reduce<BPB_I>(sred, b, chunk, /*mode=*/0, nullptr);
}

// Agreement pass: logits = bin + dot(u, vsum); c = softmax; s = sum_i c*u.
// Plain LDG.128 of fp16 u (1 mem-instr per 16B: LSU-light), priors preloaded
// from the transposed table (4 LDG.128/kernel), full-unroll 8-row loop so
// ptxas pipelines the loads. smem = 16KB sred only. 3 blocks/SM.
template<int MODE>
__global__ __launch_bounds__(THREADS, 3)
void rba_iter(float* __restrict__ out)
{
    __shared__ float sred[WPB][ROW];   // 16 KB
    const int b     = blockIdx.x >> 5;         // BPB_T = 32
    const int chunk = blockIdx.x & 31;
    const int warp  = threadIdx.x >> 5;
    const int lane  = threadIdx.x & 31;
    const int wc    = chunk * WPB + warp;      // 0..255
    const unsigned FULL = 0xffffffffu;

    // vsum packed & pre-scaled by log2(e): slot A floats [8*lane,+8), slot B +256
    u64 vpA[4], vpB[4];
    {
        const float* vb = g_vsum + (size_t)b * ROW + lane * 8;
        float4 a0 = *reinterpret_cast<const float4*>(vb);
        float4 a1 = *reinterpret_cast<const float4*>(vb + 4);
        float4 b0 = *reinterpret_cast<const float4*>(vb + 256);
        float4 b1 = *reinterpret_cast<const float4*>(vb + 260);
        vpA[0] = pack_f2(a0.x*LOG2E_F, a0.y*LOG2E_F); vpA[1] = pack_f2(a0.z*LOG2E_F, a0.w*LOG2E_F);
        vpA[2] = pack_f2(a1.x*LOG2E_F, a1.y*LOG2E_F); vpA[3] = pack_f2(a1.z*LOG2E_F, a1.w*LOG2E_F);
        vpB[0] = pack_f2(b0.x*LOG2E_F, b0.y*LOG2E_F); vpB[1] = pack_f2(b0.z*LOG2E_F, b0.w*LOG2E_F);
        vpB[2] = pack_f2(b1.x*LOG2E_F, b1.y*LOG2E_F); vpB[3] = pack_f2(b1.z*LOG2E_F, b1.w*LOG2E_F);
    }

    // logit priors for all 8 rows of both o-slots (transposed table, 4x LDG.128)
    float prA[8], prB[8];
    {
        const float* btA = g_bpre_t + (size_t)(lane >> 1) * IC + wc * IPW_T;
        const float* btB = g_bpre_t + (size_t)(16 + (lane >> 1)) * IC + wc * IPW_T;
        float4 a0 = *reinterpret_cast<const float4*>(btA);
        float4 a1 = *reinterpret_cast<const float4*>(btA + 4);
        float4 b0 = *reinterpret_cast<const float4*>(btB);
        float4 b1 = *reinterpret_cast<const float4*>(btB + 4);
        prA[0]=a0.x; prA[1]=a0.y; prA[2]=a0.z; prA[3]=a0.w;
        prA[4]=a1.x; prA[5]=a1.y; prA[6]=a1.z; prA[7]=a1.w;
        prB[0]=b0.x; prB[1]=b0.y; prB[2]=b0.z; prB[3]=b0.w;
        prB[4]=b1.x; prB[5]=b1.y; prB[6]=b1.z; prB[7]=b1.w;
    }

    u64 accA[4], accB[4];
    #pragma unroll
    for (int k = 0; k < 4; ++k) { accA[k] = 0ull; accB[k] = 0ull; }

    const __half* up = g_u16 + ((size_t)b * IC + (size_t)wc * IPW_T) * ROW;
    const int loff = lane * 8;                 // halves

    #pragma unroll
    for (int ii = 0; ii < IPW_T; ++ii) {
        // 2 LDG.128: the only in-loop memory ops (fully coalesced 512B/warp each)
        uint4 rA = *reinterpret_cast<const uint4*>(up + (size_t)ii * ROW + loff);
        uint4 rB = *reinterpret_cast<const uint4*>(up + (size_t)ii * ROW + 256 + loff);

        u64 uPA[4], uPB[4];
        {
            const __half2* hA = reinterpret_cast<const __half2*>(&rA);
            const __half2* hB = reinterpret_cast<const __half2*>(&rB);
            #pragma unroll
            for (int k = 0; k < 4; ++k) {
                float2 fa = __half22float2(hA[k]);
                float2 fb = __half22float2(hB[k]);
                uPA[k] = pack_f2(fa.x, fa.y);
                uPB[k] = pack_f2(fb.x, fb.y);
            }
        }

        // packed dots (pre-scaled by log2e via v)
        u64 dA = 0ull, dB = 0ull;
        #pragma unroll
        for (int k = 0; k < 4; ++k) { ffma2(dA, uPA[k], vpA[k]); ffma2(dB, uPB[k], vpB[k]); }
        float xl, xh;
        unpack_f2(dA, xl, xh); float pA = xl + xh;
        unpack_f2(dB, xl, xh); float pB = xl + xh;
        pA += __shfl_xor_sync(FULL, pA, 1);   // full d-dot within lane pair
        pB += __shfl_xor_sync(FULL, pB, 1);

        float eA = ex2a(prA[ii] + pA);
        float eB = ex2a(prB[ii] + pB);
        float Z  = eA + eB;
        // xor{2,4,8,16} sums each of the 32 output caps exactly once
        Z += __shfl_xor_sync(FULL, Z, 2);
        Z += __shfl_xor_sync(FULL, Z, 4);
        Z += __shfl_xor_sync(FULL, Z, 8);
        Z += __shfl_xor_sync(FULL, Z, 16);
        float rZ = rcpa(Z);
        u64 cAp = pack_f2(eA * rZ, eA * rZ);
        u64 cBp = pack_f2(eB * rZ, eB * rZ);

        #pragma unroll
        for (int k = 0; k < 4; ++k) { ffma2(accA[k], cAp, uPA[k]); ffma2(accB[k], cBp, uPB[k]); }
    }

    float aa[8], bb[8];
    #pragma unroll
    for (int k = 0; k < 4; ++k) {
        unpack_f2(accA[k], aa[2*k], aa[2*k+1]);
        unpack_f2(accB[k], bb[2*k], bb[2*k+1]);
    }
    float* w0 = &sred[warp][lane * 8];
    *reinterpret_cast<float4*>(w0)       = make_float4(aa[0], aa[1], aa[2], aa[3]);
    *reinterpret_cast<float4*>(w0 + 4)   = make_float4(aa[4], aa[5], aa[6], aa[7]);
    *reinterpret_cast<float4*>(w0 + 256) = make_float4(bb[0], bb[1], bb[2], bb[3]);
    *reinterpret_cast<float4*>(w0 + 260) = make_float4(bb[4], bb[5], bb[6], bb[7]);
    __syncthreads();
    block_tail_reduce<BPB_T>(sred, b, chunk, MODE, out);
}

extern "C" void kernel_launch(void* const* d_in, const int* in_sizes, int n_in,
                              void* d_out, int out_size)
{
    const float* u   = (const float*)d_in[0];  // [128,2048,32,16] f32
    const float* bin = (const float*)d_in[1];  // [2048,32] f32
    float* out = (float*)d_out;                // [128,32,16] f32

    // pre-scale + transpose logit priors once
    rba_prescale<<<(IC * OC + 255) / 256, 256>>>(bin);

    // v0 = squash(sum c0*u), c0 = softmax(bin); emit fp16 u; vsum = v0
    rba_init<<<BATCH * BPB_I, THREADS>>>(u, bin);
    // iter1: logits = bin + u.v0          ; vsum += v1
    rba_iter<1><<<BATCH * BPB_T, THREADS>>>(out);
    // iter2: logits = bin + u.(v0+v1)     ; vsum += v2
    rba_iter<1><<<BATCH * BPB_T, THREADS>>>(out);
    // iter3: logits = bin + u.(v0+v1+v2)  ; out = v3
    rba_iter<2><<<BATCH * BPB_T, THREADS>>>(out);

    (void)in_sizes; (void)n_in; (void)out_size;
}

// round 10
// speedup vs baseline: 1.0593x; 1.0593x over previous
#include <cuda_runtime.h>
#include <cuda_fp16.h>
#include <cstdint>

// Problem constants (fixed by setup_inputs)
#define BATCH 128
#define IC    2048
#define OC    32
#define OD    16
#define ROW   512          // OC*OD floats per (b,i) row
#define THREADS 256
#define WPB   8            // warps per block
#define BPB_I 8            // blocks per batch, init pass
#define BPB_T 32           // blocks per batch, iter passes (grid 4096)
#define IPW_I 32           // rows per warp, init
#define IPW_T 8            // rows per warp, iter
#define DEPTH 4            // smem staging ring depth (rows)
#define SPLIT_B 52         // batches 0..51 of u16 (104 MB) pinned in L2 (evict_last)

typedef unsigned long long u64;
#define LOG2E_F 1.4426950408889634f

// Scratch (device globals: allocation-free per harness rules)
__device__ __align__(16) __half g_u16[(size_t)BATCH * IC * ROW];    // 268 MB fp16 copy of u
__device__ __align__(16) float  g_part[(size_t)BATCH * BPB_T * ROW];// 8 MB block partials
__device__ __align__(16) float  g_vsum[(size_t)BATCH * ROW];        // 256 KB running v sum
__device__ __align__(16) float  g_bpre[(size_t)IC * OC];            // 256 KB bin * log2(e)
__device__ int g_cnt[BATCH];                                        // zero-init; self-resetting

// L2 cache policies (per-thread register, block-uniform selection)
__device__ __forceinline__ u64 pol_evict_last() {
    u64 p; asm("createpolicy.fractional.L2::evict_last.b64 %0, 1.0;" : "=l"(p)); return p;
}
__device__ __forceinline__ u64 pol_evict_first() {
    u64 p; asm("createpolicy.fractional.L2::evict_first.b64 %0, 1.0;" : "=l"(p)); return p;
}
__device__ __forceinline__ void cp_async16_pol(unsigned saddr, const void* gptr, u64 pol) {
    asm volatile("cp.async.cg.shared.global.L2::cache_hint [%0], [%1], 16, %2;\n"
                 :: "r"(saddr), "l"(gptr), "l"(pol) : "memory");
}
__device__ __forceinline__ void st8_pol(__half* p, uint2 v, u64 pol) {
    asm volatile("st.global.L2::cache_hint.v2.u32 [%0], {%1, %2}, %3;"
                 :: "l"(p), "r"(v.x), "r"(v.y), "l"(pol) : "memory");
}

__device__ __forceinline__ u64 pack_f2(float lo, float hi) {
    u64 r; asm("mov.b64 %0, {%1, %2};" : "=l"(r) : "f"(lo), "f"(hi)); return r;
}
__device__ __forceinline__ void unpack_f2(u64 v, float& lo, float& hi) {
    asm("mov.b64 {%0, %1}, %2;" : "=f"(lo), "=f"(hi) : "l"(v));
}
__device__ __forceinline__ void ffma2(u64& d, u64 a, u64 b) {
    asm("fma.rn.f32x2 %0, %1, %2, %0;" : "+l"(d) : "l"(a), "l"(b));
}
__device__ __forceinline__ float ex2a(float x) {
    float y; asm("ex2.approx.f32 %0, %1;" : "=f"(y) : "f"(x)); return y;
}
__device__ __forceinline__ float rcpa(float x) {
    float y; asm("rcp.approx.f32 %0, %1;" : "=f"(y) : "f"(x)); return y;
}

// Tiny one-shot: g_bpre = bin * log2(e)
__global__ void rba_prescale(const float* __restrict__ bin)
{
    int idx = blockIdx.x * blockDim.x + threadIdx.x;
    if (idx < IC * OC) g_bpre[idx] = bin[idx] * LOG2E_F;
}

// Cross-block reduction + squash, after warp partials are in sred.
// NB = chunks per batch. mode 0: vsum = v; mode 1: vsum += v; mode 2: out = v.
template<int NB>
__device__ __forceinline__ void block_tail_reduce(float (*sred)[ROW], int b, int chunk,
                                                  int mode, float* __restrict__ out)
{
    __shared__ bool amLast;
    const int t = threadIdx.x;
    float r0 = 0.f, r1 = 0.f;
    #pragma unroll
    for (int w = 0; w < WPB; ++w) { r0 += sred[w][t]; r1 += sred[w][t + 256]; }
    float* bp = g_part + ((size_t)b * NB + chunk) * ROW;
    bp[t] = r0; bp[t + 256] = r1;

    __threadfence();
    __syncthreads();
    if (t == 0) {
        int old = atomicAdd(&g_cnt[b], 1);
        amLast = (old == NB - 1);
        if (amLast) g_cnt[b] = 0;      // replay-safe reset
    }
    __syncthreads();
    if (!amLast) return;
    __threadfence();                   // acquire: see all blocks' partials

    const float* pb = g_part + (size_t)b * NB * ROW;
    float s0 = 0.f, s1 = 0.f;
    #pragma unroll 8
    for (int c = 0; c < NB; ++c) {     // fixed order -> deterministic
        s0 += pb[(size_t)c * ROW + t];
        s1 += pb[(size_t)c * ROW + t + 256];
    }

    // squash: ||s||^2 over the 16 d-lanes of each o
    const unsigned FULL = 0xffffffffu;
    float q0 = s0 * s0, q1 = s1 * s1;
    #pragma unroll
    for (int m = 1; m < 16; m <<= 1) {
        q0 += __shfl_xor_sync(FULL, q0, m);
        q1 += __shfl_xor_sync(FULL, q1, m);
    }
    float v0 = s0 * sqrtf(q0) / (1.f + q0);
    float v1 = s1 * sqrtf(q1) / (1.f + q1);

    float* vs = g_vsum + (size_t)b * ROW;
    if (mode == 0)      { vs[t] = v0;            vs[t + 256] = v1; }
    else if (mode == 1) { vs[t] += v0;           vs[t + 256] += v1; }
    else                { out[(size_t)b * ROW + t] = v0;
                          out[(size_t)b * ROW + t + 256] = v1; }
}

// Init pass: c = softmax(b_in), s = sum_i c*u; emits fp16 copy of u.
// u16 stores: batches < SPLIT_B pinned via L2 evict_last (persist across the
// three iter passes); the rest evict_first (pure write-stream).
__global__ __launch_bounds__(THREADS)
void rba_init(const float* __restrict__ u, const float* __restrict__ bin)
{
    __shared__ float sred[WPB][ROW];
    const int b     = blockIdx.x >> 3;
    const int chunk = blockIdx.x & 7;
    const int warp  = threadIdx.x >> 5;
    const int lane  = threadIdx.x & 31;
    const int g     = lane >> 2;
    const int wc    = chunk * WPB + warp;
    const unsigned FULL = 0xffffffffu;

    const u64 pol = (b < SPLIT_B) ? pol_evict_last() : pol_evict_first();

    float4 acc[4];
    #pragma unroll
    for (int j = 0; j < 4; ++j) acc[j] = make_float4(0.f, 0.f, 0.f, 0.f);

    const size_t ubase = ((size_t)b * IC + (size_t)wc * IPW_I) * ROW;

    for (int ii = 0; ii < IPW_I; ++ii) {
        const int i = wc * IPW_I + ii;
        const float4* up = reinterpret_cast<const float4*>(u + ubase + (size_t)ii * ROW);
        __half* dst = g_u16 + ubase + (size_t)ii * ROW;

        float4 u4[4];
        #pragma unroll
        for (int j = 0; j < 4; ++j) u4[j] = up[j * 32 + lane];   // coalesced 2KB/row

        #pragma unroll
        for (int j = 0; j < 4; ++j) {
            union { uint2 raw; __half2 h[2]; } pk;
            pk.h[0] = __floats2half2_rn(u4[j].x, u4[j].y);
            pk.h[1] = __floats2half2_rn(u4[j].z, u4[j].w);
            st8_pol(dst + j * 128 + lane * 4, pk.raw, pol);
        }

        float bv = bin[(size_t)i * OC + lane];
        float logit[4];
        #pragma unroll
        for (int j = 0; j < 4; ++j) logit[j] = __shfl_sync(FULL, bv, j * 8 + g);

        float e[4], Z = 0.f;
        #pragma unroll
        for (int j = 0; j < 4; ++j) { e[j] = __expf(logit[j]); Z += e[j]; }
        Z += __shfl_xor_sync(FULL, Z, 4);
        Z += __shfl_xor_sync(FULL, Z, 8);
        Z += __shfl_xor_sync(FULL, Z, 16);
        float rZ = __frcp_rn(Z);
        #pragma unroll
        for (int j = 0; j < 4; ++j) {
            float c = e[j] * rZ;
            acc[j].x += c * u4[j].x; acc[j].y += c * u4[j].y;
            acc[j].z += c * u4[j].z; acc[j].w += c * u4[j].w;
        }
    }

    #pragma unroll
    for (int j = 0; j < 4; ++j)
        *reinterpret_cast<float4*>(&sred[warp][j * 128 + lane * 4]) = acc[j];
    __syncthreads();
    block_tail_reduce<BPB_I>(sred, b, chunk, /*mode=*/0, nullptr);
}

// Agreement pass (R8 structure): logits = bin + dot(u, vsum); c = softmax;
// s = sum_i c*u. fp16 u via cp.async 4-row smem ring with L2 policy:
// batches < SPLIT_B hit the pinned L2 region (evict_last), rest stream
// (evict_first). Base-2 exponentials; packed f32x2 FMA; sred aliases the
// stage; 4 blocks/SM.
template<int MODE>
__global__ __launch_bounds__(THREADS, 4)
void rba_iter(float* __restrict__ out)
{
    __shared__ __align__(16) char smem_raw[WPB * DEPTH * ROW * 2];   // 32 KB
    __half (*stage)[DEPTH][ROW] = reinterpret_cast<__half(*)[DEPTH][ROW]>(smem_raw);
    float  (*sred)[ROW]         = reinterpret_cast<float(*)[ROW]>(smem_raw);

    const int b     = blockIdx.x >> 5;         // BPB_T = 32
    const int chunk = blockIdx.x & 31;
    const int warp  = threadIdx.x >> 5;
    const int lane  = threadIdx.x & 31;
    const int wc    = chunk * WPB + warp;      // 0..255
    const unsigned FULL = 0xffffffffu;

    const u64 pol = (b < SPLIT_B) ? pol_evict_last() : pol_evict_first();

    // vsum packed & pre-scaled by log2(e): slot A floats [8*lane,+8), slot B +256
    u64 vpA[4], vpB[4];
    {
        const float* vb = g_vsum + (size_t)b * ROW + lane * 8;
        float4 a0 = *reinterpret_cast<const float4*>(vb);
        float4 a1 = *reinterpret_cast<const float4*>(vb + 4);
        float4 b0 = *reinterpret_cast<const float4*>(vb + 256);
        float4 b1 = *reinterpret_cast<const float4*>(vb + 260);
        vpA[0] = pack_f2(a0.x*LOG2E_F, a0.y*LOG2E_F); vpA[1] = pack_f2(a0.z*LOG2E_F, a0.w*LOG2E_F);
        vpA[2] = pack_f2(a1.x*LOG2E_F, a1.y*LOG2E_F); vpA[3] = pack_f2(a1.z*LOG2E_F, a1.w*LOG2E_F);
        vpB[0] = pack_f2(b0.x*LOG2E_F, b0.y*LOG2E_F); vpB[1] = pack_f2(b0.z*LOG2E_F, b0.w*LOG2E_F);
        vpB[2] = pack_f2(b1.x*LOG2E_F, b1.y*LOG2E_F); vpB[3] = pack_f2(b1.z*LOG2E_F, b1.w*LOG2E_F);
    }

    u64 accA[4], accB[4];
    #pragma unroll
    for (int k = 0; k < 4; ++k) { accA[k] = 0ull; accB[k] = 0ull; }

    const __half* up = g_u16 + ((size_t)b * IC + (size_t)wc * IPW_T) * ROW;
    const float* bp0 = g_bpre + (size_t)(wc * IPW_T) * OC + (lane >> 1);
    const int loff = lane * 8;                 // halves

    const unsigned sbase =
        (unsigned)__cvta_generic_to_shared(&stage[warp][0][0]) + loff * 2;

    // prologue: rows 0..2 in flight (3 groups)
    #pragma unroll
    for (int p = 0; p < 3; ++p) {
        const __half* g = up + (size_t)p * ROW + loff;
        cp_async16_pol(sbase + p * (ROW * 2), g, pol);
        cp_async16_pol(sbase + p * (ROW * 2) + 512, g + 256, pol);
        asm volatile("cp.async.commit_group;\n" ::: "memory");
    }

    #pragma unroll
    for (int ii = 0; ii < IPW_T; ++ii) {
        // logit priors (pre-scaled, L1-broadcast within lane pairs)
        float blA = bp0[ii * OC];
        float blB = bp0[ii * OC + 16];

        const int pf = ii + 3;
        if (pf < IPW_T) {
            const __half* g = up + (size_t)pf * ROW + loff;
            const unsigned sa = sbase + (pf & (DEPTH - 1)) * (ROW * 2);
            cp_async16_pol(sa, g, pol);
            cp_async16_pol(sa + 512, g + 256, pol);
        }
        asm volatile("cp.async.commit_group;\n" ::: "memory");
        asm volatile("cp.async.wait_group 3;\n" ::: "memory");   // row ii ready

        const int s = ii & (DEPTH - 1);
        uint4 rA = *reinterpret_cast<const uint4*>(&stage[warp][s][loff]);
        uint4 rB = *reinterpret_cast<const uint4*>(&stage[warp][s][256 + loff]);

        u64 uPA[4], uPB[4];
        {
            const __half2* hA = reinterpret_cast<const __half2*>(&rA);
            const __half2* hB = reinterpret_cast<const __half2*>(&rB);
            #pragma unroll
            for (int k = 0; k < 4; ++k) {
                float2 fa = __half22float2(hA[k]);
                float2 fb = __half22float2(hB[k]);
                uPA[k] = pack_f2(fa.x, fa.y);
                uPB[k] = pack_f2(fb.x, fb.y);
            }
        }

        // packed dots (pre-scaled by log2e via v)
        u64 dA = 0ull, dB = 0ull;
        #pragma unroll
        for (int k = 0; k < 4; ++k) { ffma2(dA, uPA[k], vpA[k]); ffma2(dB, uPB[k], vpB[k]); }
        float xl, xh;
        unpack_f2(dA, xl, xh); float pA = xl + xh;
        unpack_f2(dB, xl, xh); float pB = xl + xh;
        pA += __shfl_xor_sync(FULL, pA, 1);   // full d-dot within lane pair
        pB += __shfl_xor_sync(FULL, pB, 1);

        float eA = ex2a(blA + pA);
        float eB = ex2a(blB + pB);
        float Z  = eA + eB;
        // xor{2,4,8,16} sums each of the 32 output caps exactly once
        Z += __shfl_xor_sync(FULL, Z, 2);
        Z += __shfl_xor_sync(FULL, Z, 4);
        Z += __shfl_xor_sync(FULL, Z, 8);
        Z += __shfl_xor_sync(FULL, Z, 16);
        float rZ = rcpa(Z);
        u64 cAp = pack_f2(eA * rZ, eA * rZ);
        u64 cBp = pack_f2(eB * rZ, eB * rZ);

        #pragma unroll
        for (int k = 0; k < 4; ++k) { ffma2(accA[k], cAp, uPA[k]); ffma2(accB[k], cBp, uPB[k]); }
    }

    asm volatile("cp.async.wait_group 0;\n" ::: "memory");
    __syncthreads();                       // stage dead; safe to alias as sred

    float aa[8], bb[8];
    #pragma unroll
    for (int k = 0; k < 4; ++k) {
        unpack_f2(accA[k], aa[2*k], aa[2*k+1]);
        unpack_f2(accB[k], bb[2*k], bb[2*k+1]);
    }
    float* w0 = &sred[warp][lane * 8];
    *reinterpret_cast<float4*>(w0)       = make_float4(aa[0], aa[1], aa[2], aa[3]);
    *reinterpret_cast<float4*>(w0 + 4)   = make_float4(aa[4], aa[5], aa[6], aa[7]);
    *reinterpret_cast<float4*>(w0 + 256) = make_float4(bb[0], bb[1], bb[2], bb[3]);
    *reinterpret_cast<float4*>(w0 + 260) = make_float4(bb[4], bb[5], bb[6], bb[7]);
    __syncthreads();
    block_tail_reduce<BPB_T>(sred, b, chunk, MODE, out);
}

extern "C" void kernel_launch(void* const* d_in, const int* in_sizes, int n_in,
                              void* d_out, int out_size)
{
    const float* u   = (const float*)d_in[0];  // [128,2048,32,16] f32
    const float* bin = (const float*)d_in[1];  // [2048,32] f32
    float* out = (float*)d_out;                // [128,32,16] f32

    // pre-scale logit priors once
    rba_prescale<<<(IC * OC + 255) / 256, 256>>>(bin);

    // v0 = squash(sum c0*u), c0 = softmax(bin); emit fp16 u; vsum = v0
    rba_init<<<BATCH * BPB_I, THREADS>>>(u, bin);
    // iter1: logits = bin + u.v0          ; vsum += v1
    rba_iter<1><<<BATCH * BPB_T, THREADS>>>(out);
    // iter2: logits = bin + u.(v0+v1)     ; vsum += v2
    rba_iter<1><<<BATCH * BPB_T, THREADS>>>(out);
    // iter3: logits = bin + u.(v0+v1+v2)  ; out = v3
    rba_iter<2><<<BATCH * BPB_T, THREADS>>>(out);

    (void)in_sizes; (void)n_in; (void)out_size;
}